// round 1
// baseline (speedup 1.0000x reference)
#include <cuda_runtime.h>

#define BATCH 2
#define CCH   512
#define NGRP  32
#define CPG   16
#define NSP   32768
#define EPSV  1e-5f
#define KSPL  4

// ---------------- scratch (device globals; no runtime allocation) ----------
__device__ float g_xn[(size_t)BATCH * CCH * NSP];          // 128 MB normalized input
__device__ float g_chansum[BATCH * CCH];
__device__ float g_chansq[BATCH * CCH];
__device__ float g_mean[BATCH * NGRP];
__device__ float g_rstd[BATCH * NGRP];
__device__ float g_svec[BATCH * CCH];                      // per-channel row sums of xn
__device__ float g_Gp[(size_t)KSPL * BATCH * CCH * CCH];   // K-split Gram partials
__device__ float g_G[(size_t)BATCH * CCH * CCH];
__device__ float g_P[(size_t)BATCH * CCH * CCH];
__device__ float g_L[(size_t)BATCH * CCH * CCH];           // logits -> softmax in place
__device__ float g_M[(size_t)BATCH * CCH * CCH];
__device__ float g_We[(size_t)BATCH * CCH * CCH];
__device__ float g_u[BATCH * CCH];
__device__ float g_wv[BATCH * CCH];
__device__ float g_cv[BATCH * CCH];

// ---------------- packed f32x2 helpers -------------------------------------
__device__ __forceinline__ unsigned long long pack2(float lo, float hi) {
    unsigned long long r;
    asm("mov.b64 %0, {%1, %2};" : "=l"(r) : "f"(lo), "f"(hi));
    return r;
}
__device__ __forceinline__ void unpack2(unsigned long long v, float &lo, float &hi) {
    asm("mov.b64 {%0, %1}, %2;" : "=f"(lo), "=f"(hi) : "l"(v));
}
__device__ __forceinline__ void ffma2(unsigned long long &d, unsigned long long a,
                                      unsigned long long b) {
    asm("fma.rn.f32x2 %0, %1, %2, %3;" : "=l"(d) : "l"(a), "l"(b), "l"(d));
}

// ---------------- GroupNorm stage 1: per-channel sums ----------------------
__global__ void k_chansum(const float* __restrict__ x) {
    int bc = blockIdx.x;                       // b*512 + c
    const float4* row = (const float4*)(x + (size_t)bc * NSP);
    float s = 0.f, sq = 0.f;
    for (int i = threadIdx.x; i < NSP / 4; i += blockDim.x) {
        float4 v = row[i];
        s  += v.x + v.y + v.z + v.w;
        sq += v.x * v.x + v.y * v.y + v.z * v.z + v.w * v.w;
    }
    __shared__ float ss[256], ssq[256];
    ss[threadIdx.x] = s; ssq[threadIdx.x] = sq;
    __syncthreads();
    for (int st = 128; st > 0; st >>= 1) {
        if (threadIdx.x < st) {
            ss[threadIdx.x]  += ss[threadIdx.x + st];
            ssq[threadIdx.x] += ssq[threadIdx.x + st];
        }
        __syncthreads();
    }
    if (threadIdx.x == 0) { g_chansum[bc] = ss[0]; g_chansq[bc] = ssq[0]; }
}

// ---------------- GroupNorm stage 2: group stats + channel row-sums --------
__global__ void k_stats(const float* __restrict__ gn_w, const float* __restrict__ gn_b) {
    __shared__ float sm[BATCH * NGRP], sr[BATCH * NGRP];
    int t = threadIdx.x;
    if (t < BATCH * NGRP) {
        float s = 0.f, sq = 0.f;
        for (int c = 0; c < CPG; c++) { s += g_chansum[t * CPG + c]; sq += g_chansq[t * CPG + c]; }
        float inv  = 1.f / ((float)CPG * (float)NSP);
        float mean = s * inv;
        float var  = sq * inv - mean * mean;
        float rstd = rsqrtf(var + EPSV);
        g_mean[t] = mean; g_rstd[t] = rstd;
        sm[t] = mean; sr[t] = rstd;
    }
    __syncthreads();
    for (int bc = t; bc < BATCH * CCH; bc += blockDim.x) {
        int grp = bc / CPG;
        int c   = bc % CCH;
        float sv = (g_chansum[bc] - (float)NSP * sm[grp]) * sr[grp] * gn_w[c]
                 + (float)NSP * gn_b[c];
        g_svec[bc] = sv;
    }
}

// ---------------- GroupNorm stage 3: write xn -------------------------------
__global__ void k_xn(const float* __restrict__ x, const float* __restrict__ gn_w,
                     const float* __restrict__ gn_b) {
    int bc  = blockIdx.x;
    int grp = bc / CPG;
    int c   = bc % CCH;
    float a  = g_rstd[grp] * gn_w[c];
    float bb = gn_b[c] - g_mean[grp] * a;
    const float4* src = (const float4*)(x + (size_t)bc * NSP);
    float4* dst = (float4*)(g_xn + (size_t)bc * NSP);
    for (int i = threadIdx.x; i < NSP / 4; i += blockDim.x) {
        float4 v = src[i];
        v.x = v.x * a + bb; v.y = v.y * a + bb; v.z = v.z * a + bb; v.w = v.w * a + bb;
        dst[i] = v;
    }
}

// ---------------- Gram: G = xn @ xn^T, upper-tri tiles, K-split -------------
__global__ void __launch_bounds__(256) k_gram() {
    int tri = blockIdx.x, ks = blockIdx.y, b = blockIdx.z;
    int bi = 0, rem = tri;
    while (rem >= 8 - bi) { rem -= 8 - bi; bi++; }
    int bj = bi + rem;

    const float* base = g_xn + (size_t)b * CCH * NSP;
    __shared__ __align__(16) float As[16][68];
    __shared__ __align__(16) float Bs[16][68];
    int tid = threadIdx.x;
    int ty = tid >> 4, tx = tid & 15;
    int lr = tid >> 2, lc = (tid & 3) << 2;
    const int KCH = NSP / KSPL;

    const float* aptr = base + (size_t)(bi * 64 + lr) * NSP + ks * KCH + lc;
    const float* bptr = base + (size_t)(bj * 64 + lr) * NSP + ks * KCH + lc;

    unsigned long long acc[4][2];
#pragma unroll
    for (int i = 0; i < 4; i++) { acc[i][0] = 0ull; acc[i][1] = 0ull; }

    float4 av = *(const float4*)aptr;
    float4 bv = *(const float4*)bptr;

    for (int k0 = 0; k0 < KCH; k0 += 16) {
        __syncthreads();
        As[lc + 0][lr] = av.x; As[lc + 1][lr] = av.y; As[lc + 2][lr] = av.z; As[lc + 3][lr] = av.w;
        Bs[lc + 0][lr] = bv.x; Bs[lc + 1][lr] = bv.y; Bs[lc + 2][lr] = bv.z; Bs[lc + 3][lr] = bv.w;
        __syncthreads();
        if (k0 + 16 < KCH) {
            av = *(const float4*)(aptr + k0 + 16);
            bv = *(const float4*)(bptr + k0 + 16);
        }
#pragma unroll
        for (int kk = 0; kk < 16; kk++) {
            float4 a = *(const float4*)&As[kk][ty << 2];
            unsigned long long ap0 = pack2(a.x, a.x), ap1 = pack2(a.y, a.y);
            unsigned long long ap2 = pack2(a.z, a.z), ap3 = pack2(a.w, a.w);
            ulonglong2 bb = *(const ulonglong2*)&Bs[kk][tx << 2];
            ffma2(acc[0][0], ap0, bb.x); ffma2(acc[0][1], ap0, bb.y);
            ffma2(acc[1][0], ap1, bb.x); ffma2(acc[1][1], ap1, bb.y);
            ffma2(acc[2][0], ap2, bb.x); ffma2(acc[2][1], ap2, bb.y);
            ffma2(acc[3][0], ap3, bb.x); ffma2(acc[3][1], ap3, bb.y);
        }
    }

    float* Gp = g_Gp + ((size_t)ks * BATCH + b) * CCH * CCH;
    int gi0 = bi * 64 + (ty << 2);
    int gj0 = bj * 64 + (tx << 2);
#pragma unroll
    for (int i = 0; i < 4; i++) {
#pragma unroll
        for (int jp = 0; jp < 2; jp++) {
            float lo, hi; unpack2(acc[i][jp], lo, hi);
            int gi = gi0 + i, gj = gj0 + (jp << 1);
            Gp[(size_t)gi * CCH + gj]     = lo;
            Gp[(size_t)gi * CCH + gj + 1] = hi;
            if (bi != bj) {
                Gp[(size_t)gj * CCH + gi]       = lo;
                Gp[(size_t)(gj + 1) * CCH + gi] = hi;
            }
        }
    }
}

// ---------------- reduce K-split Gram partials ------------------------------
__global__ void k_gsum() {
    size_t i = (size_t)blockIdx.x * blockDim.x + threadIdx.x;   // < BATCH*CCH*CCH
    const size_t stride = (size_t)BATCH * CCH * CCH;
    g_G[i] = (g_Gp[i] + g_Gp[i + stride]) + (g_Gp[i + 2 * stride] + g_Gp[i + 3 * stride]);
}

// ---------------- u = Wq@s, w = Wk@s ----------------------------------------
__global__ void k_uv(const float* __restrict__ qkv_w) {
    int idx = blockIdx.x * blockDim.x + threadIdx.x;   // 0..2047
    int b     = idx >> 10;
    int which = (idx >> 9) & 1;
    int row   = idx & 511;
    const float* W = qkv_w + (size_t)(which * CCH + row) * CCH;
    const float* s = g_svec + b * CCH;
    float acc = 0.f;
    for (int c = 0; c < CCH; c++) acc += W[c] * s[c];
    if (which == 0) g_u[b * CCH + row] = acc; else g_wv[b * CCH + row] = acc;
}

// ---------------- generic small NN GEMM: 3 uses ------------------------------
// mode 0: P   = Wq    @ G[b]
// mode 1: M   = projw @ A[b]   (A = softmaxed g_L)
// mode 2: We  = M[b]  @ Wv
__global__ void __launch_bounds__(256) k_small_nn(int mode, const float* __restrict__ qkv_w,
                                                  const float* __restrict__ proj_w) {
    int bjt = blockIdx.x, bit = blockIdx.y, b = blockIdx.z;
    const float *A, *B; float* C;
    if (mode == 0)      { A = qkv_w;                         B = g_G + (size_t)b * CCH * CCH; C = g_P  + (size_t)b * CCH * CCH; }
    else if (mode == 1) { A = proj_w;                        B = g_L + (size_t)b * CCH * CCH; C = g_M  + (size_t)b * CCH * CCH; }
    else                { A = g_M + (size_t)b * CCH * CCH;   B = qkv_w + (size_t)1024 * CCH;  C = g_We + (size_t)b * CCH * CCH; }

    __shared__ __align__(16) float As[16][68];
    __shared__ __align__(16) float Bs[16][64];
    int tid = threadIdx.x, ty = tid >> 4, tx = tid & 15;
    int alr = tid >> 2, alc = (tid & 3) << 2;
    int br = tid >> 4, bc = (tid & 15) << 2;
    const float* aptr = A + (size_t)(bit * 64 + alr) * CCH + alc;
    const float* bptr = B + (size_t)br * CCH + bjt * 64 + bc;

    float acc[4][4] = {};
    for (int k0 = 0; k0 < CCH; k0 += 16) {
        float4 av = *(const float4*)(aptr + k0);
        float4 bv = *(const float4*)(bptr + (size_t)k0 * CCH);
        __syncthreads();
        As[alc + 0][alr] = av.x; As[alc + 1][alr] = av.y;
        As[alc + 2][alr] = av.z; As[alc + 3][alr] = av.w;
        *(float4*)&Bs[br][bc] = bv;
        __syncthreads();
#pragma unroll
        for (int kk = 0; kk < 16; kk++) {
            float4 a  = *(const float4*)&As[kk][ty << 2];
            float4 bb = *(const float4*)&Bs[kk][tx << 2];
            acc[0][0] += a.x * bb.x; acc[0][1] += a.x * bb.y; acc[0][2] += a.x * bb.z; acc[0][3] += a.x * bb.w;
            acc[1][0] += a.y * bb.x; acc[1][1] += a.y * bb.y; acc[1][2] += a.y * bb.z; acc[1][3] += a.y * bb.w;
            acc[2][0] += a.z * bb.x; acc[2][1] += a.z * bb.y; acc[2][2] += a.z * bb.z; acc[2][3] += a.z * bb.w;
            acc[3][0] += a.w * bb.x; acc[3][1] += a.w * bb.y; acc[3][2] += a.w * bb.z; acc[3][3] += a.w * bb.w;
        }
    }
    int gi0 = bit * 64 + (ty << 2), gj0 = bjt * 64 + (tx << 2);
#pragma unroll
    for (int i = 0; i < 4; i++)
#pragma unroll
        for (int j = 0; j < 4; j++)
            C[(size_t)(gi0 + i) * CCH + gj0 + j] = acc[i][j];
}

// ---------------- logits: L = scale*(P@Wk^T + rank-1 bias terms) ------------
__global__ void __launch_bounds__(256) k_nt_logits(const float* __restrict__ qkv_w,
                                                   const float* __restrict__ qkv_b) {
    int bjt = blockIdx.x, bit = blockIdx.y, b = blockIdx.z;
    const float* A  = g_P + (size_t)b * CCH * CCH;
    const float* Bm = qkv_w + (size_t)CCH * CCH;   // Wk rows
    __shared__ __align__(16) float As[16][68];
    __shared__ __align__(16) float Bs[16][68];
    int tid = threadIdx.x, ty = tid >> 4, tx = tid & 15;
    int lr = tid >> 2, lc = (tid & 3) << 2;
    const float* aptr = A  + (size_t)(bit * 64 + lr) * CCH + lc;
    const float* bptr = Bm + (size_t)(bjt * 64 + lr) * CCH + lc;

    float acc[4][4] = {};
    for (int k0 = 0; k0 < CCH; k0 += 16) {
        float4 av = *(const float4*)(aptr + k0);
        float4 bv = *(const float4*)(bptr + k0);
        __syncthreads();
        As[lc + 0][lr] = av.x; As[lc + 1][lr] = av.y; As[lc + 2][lr] = av.z; As[lc + 3][lr] = av.w;
        Bs[lc + 0][lr] = bv.x; Bs[lc + 1][lr] = bv.y; Bs[lc + 2][lr] = bv.z; Bs[lc + 3][lr] = bv.w;
        __syncthreads();
#pragma unroll
        for (int kk = 0; kk < 16; kk++) {
            float4 a  = *(const float4*)&As[kk][ty << 2];
            float4 bb = *(const float4*)&Bs[kk][tx << 2];
            acc[0][0] += a.x * bb.x; acc[0][1] += a.x * bb.y; acc[0][2] += a.x * bb.z; acc[0][3] += a.x * bb.w;
            acc[1][0] += a.y * bb.x; acc[1][1] += a.y * bb.y; acc[1][2] += a.y * bb.z; acc[1][3] += a.y * bb.w;
            acc[2][0] += a.z * bb.x; acc[2][1] += a.z * bb.y; acc[2][2] += a.z * bb.z; acc[2][3] += a.z * bb.w;
            acc[3][0] += a.w * bb.x; acc[3][1] += a.w * bb.y; acc[3][2] += a.w * bb.z; acc[3][3] += a.w * bb.w;
        }
    }
    const float scale = 0.04419417382415922f;   // 1/sqrt(512)
    const float* u = g_u  + b * CCH;
    const float* w = g_wv + b * CCH;
    float* L = g_L + (size_t)b * CCH * CCH;
    int gi0 = bit * 64 + (ty << 2), gj0 = bjt * 64 + (tx << 2);
#pragma unroll
    for (int i = 0; i < 4; i++) {
        int gi = gi0 + i;
        float bq = qkv_b[gi];
        float ui = u[gi];
#pragma unroll
        for (int j = 0; j < 4; j++) {
            int gj = gj0 + j;
            float bk = qkv_b[CCH + gj];
            float val = acc[i][j] + bq * w[gj] + bk * ui + (float)NSP * bq * bk;
            L[(size_t)gi * CCH + gj] = val * scale;
        }
    }
}

// ---------------- softmax over last dim of L (in place) ---------------------
__global__ void k_softmax() {
    int row = blockIdx.x;                        // b*512 + i
    float* L = g_L + (size_t)row * CCH;
    __shared__ float red[256];
    int t = threadIdx.x;
    float v0 = L[t], v1 = L[t + 256];
    red[t] = fmaxf(v0, v1);
    __syncthreads();
    for (int st = 128; st > 0; st >>= 1) {
        if (t < st) red[t] = fmaxf(red[t], red[t + st]);
        __syncthreads();
    }
    float mx = red[0];
    __syncthreads();
    float e0 = expf(v0 - mx), e1 = expf(v1 - mx);
    red[t] = e0 + e1;
    __syncthreads();
    for (int st = 128; st > 0; st >>= 1) {
        if (t < st) red[t] += red[t + st];
        __syncthreads();
    }
    float inv = 1.f / red[0];
    L[t] = e0 * inv; L[t + 256] = e1 * inv;
}

// ---------------- cv = M @ bv + proj_b ---------------------------------------
__global__ void k_cv(const float* __restrict__ qkv_b, const float* __restrict__ proj_b) {
    int idx = blockIdx.x * blockDim.x + threadIdx.x;   // 0..1023
    int b = idx >> 9, o = idx & 511;
    const float* M = g_M + (size_t)b * CCH * CCH + (size_t)o * CCH;
    float acc = proj_b[o];
    for (int d = 0; d < CCH; d++) acc += M[d] * qkv_b[1024 + d];
    g_cv[idx] = acc;
}

// ---------------- final: out = x + We @ xn + cv ------------------------------
__global__ void __launch_bounds__(256) k_final(const float* __restrict__ x,
                                               float* __restrict__ out) {
    int bn = blockIdx.x, bo = blockIdx.y, b = blockIdx.z;
    const float* A = g_We + (size_t)b * CCH * CCH;
    const float* B = g_xn + (size_t)b * CCH * NSP;
    __shared__ __align__(16) float As[16][68];
    __shared__ __align__(16) float Bs[16][128];
    int tid = threadIdx.x;
    int ty = tid >> 4, tx = tid & 15;
    int alr = tid >> 2, alc = (tid & 3) << 2;
    int blr = tid >> 4, blc = (tid & 15) << 3;
    const float* aptr = A + (size_t)(bo * 64 + alr) * CCH + alc;
    const float* bptr = B + (size_t)blr * NSP + bn * 128 + blc;

    unsigned long long acc[4][4];
#pragma unroll
    for (int i = 0; i < 4; i++)
#pragma unroll
        for (int j = 0; j < 4; j++) acc[i][j] = 0ull;

    float4 av  = *(const float4*)aptr;
    float4 bv0 = *(const float4*)bptr;
    float4 bv1 = *(const float4*)(bptr + 4);

    for (int k0 = 0; k0 < CCH; k0 += 16) {
        __syncthreads();
        As[alc + 0][alr] = av.x; As[alc + 1][alr] = av.y;
        As[alc + 2][alr] = av.z; As[alc + 3][alr] = av.w;
        *(float4*)&Bs[blr][blc]     = bv0;
        *(float4*)&Bs[blr][blc + 4] = bv1;
        __syncthreads();
        if (k0 + 16 < CCH) {
            av = *(const float4*)(aptr + k0 + 16);
            const float* nb = bptr + (size_t)(k0 + 16) * NSP;
            bv0 = *(const float4*)nb;
            bv1 = *(const float4*)(nb + 4);
        }
#pragma unroll
        for (int kk = 0; kk < 16; kk++) {
            float4 a = *(const float4*)&As[kk][ty << 2];
            unsigned long long ap0 = pack2(a.x, a.x), ap1 = pack2(a.y, a.y);
            unsigned long long ap2 = pack2(a.z, a.z), ap3 = pack2(a.w, a.w);
            ulonglong2 q0 = *(const ulonglong2*)&Bs[kk][tx << 3];
            ulonglong2 q1 = *(const ulonglong2*)&Bs[kk][(tx << 3) + 4];
            ffma2(acc[0][0], ap0, q0.x); ffma2(acc[0][1], ap0, q0.y);
            ffma2(acc[0][2], ap0, q1.x); ffma2(acc[0][3], ap0, q1.y);
            ffma2(acc[1][0], ap1, q0.x); ffma2(acc[1][1], ap1, q0.y);
            ffma2(acc[1][2], ap1, q1.x); ffma2(acc[1][3], ap1, q1.y);
            ffma2(acc[2][0], ap2, q0.x); ffma2(acc[2][1], ap2, q0.y);
            ffma2(acc[2][2], ap2, q1.x); ffma2(acc[2][3], ap2, q1.y);
            ffma2(acc[3][0], ap3, q0.x); ffma2(acc[3][1], ap3, q0.y);
            ffma2(acc[3][2], ap3, q1.x); ffma2(acc[3][3], ap3, q1.y);
        }
    }

    int gi0 = bo * 64 + (ty << 2);
    int n0  = bn * 128 + (tx << 3);
    const float* cvp = g_cv + b * CCH;
#pragma unroll
    for (int i = 0; i < 4; i++) {
        int gi = gi0 + i;
        float cadd = cvp[gi];
        size_t off = ((size_t)b * CCH + gi) * NSP + n0;
        float4 x0 = *(const float4*)(x + off);
        float4 x1 = *(const float4*)(x + off + 4);
        float l0, h0, l1, h1, l2, h2, l3, h3;
        unpack2(acc[i][0], l0, h0); unpack2(acc[i][1], l1, h1);
        unpack2(acc[i][2], l2, h2); unpack2(acc[i][3], l3, h3);
        float4 o0 = make_float4(x0.x + l0 + cadd, x0.y + h0 + cadd,
                                x0.z + l1 + cadd, x0.w + h1 + cadd);
        float4 o1 = make_float4(x1.x + l2 + cadd, x1.y + h2 + cadd,
                                x1.z + l3 + cadd, x1.w + h3 + cadd);
        *(float4*)(out + off)     = o0;
        *(float4*)(out + off + 4) = o1;
    }
}

// ---------------- launch ------------------------------------------------------
extern "C" void kernel_launch(void* const* d_in, const int* in_sizes, int n_in,
                              void* d_out, int out_size) {
    const float* x      = (const float*)d_in[0];
    const float* gn_w   = (const float*)d_in[1];
    const float* gn_b   = (const float*)d_in[2];
    const float* qkv_w  = (const float*)d_in[3];
    const float* qkv_b  = (const float*)d_in[4];
    const float* proj_w = (const float*)d_in[5];
    const float* proj_b = (const float*)d_in[6];
    float* out = (float*)d_out;

    k_chansum<<<BATCH * CCH, 256>>>(x);
    k_stats<<<1, 256>>>(gn_w, gn_b);
    k_xn<<<BATCH * CCH, 256>>>(x, gn_w, gn_b);
    k_gram<<<dim3(36, KSPL, BATCH), 256>>>();
    k_gsum<<<(BATCH * CCH * CCH) / 256, 256>>>();
    k_uv<<<8, 256>>>(qkv_w);
    k_small_nn<<<dim3(8, 8, BATCH), 256>>>(0, qkv_w, proj_w);   // P = Wq @ G
    k_nt_logits<<<dim3(8, 8, BATCH), 256>>>(qkv_w, qkv_b);      // L = scale*(P@Wk^T + bias)
    k_softmax<<<BATCH * CCH, 256>>>();                           // A = softmax(L)
    k_small_nn<<<dim3(8, 8, BATCH), 256>>>(1, qkv_w, proj_w);   // M = proj_w @ A
    k_small_nn<<<dim3(8, 8, BATCH), 256>>>(2, qkv_w, proj_w);   // We = M @ Wv
    k_cv<<<4, 256>>>(qkv_b, proj_b);
    k_final<<<dim3(NSP / 128, 8, BATCH), 256>>>(x, out);         // out = x + We@xn + cv
}

// round 3
// speedup vs baseline: 1.2188x; 1.2188x over previous
#include <cuda_runtime.h>

#define BATCH 2
#define CCH   512
#define NGRP  32
#define CPG   16
#define NSP   32768
#define EPSV  1e-5f
#define KSPL  32

// ---------------- scratch (device globals; no runtime allocation) ----------
__device__ float g_xn[(size_t)BATCH * CCH * NSP];          // 128 MB normalized input
__device__ float g_chansum[BATCH * CCH];
__device__ float g_chansq[BATCH * CCH];
__device__ float g_mean[BATCH * NGRP];
__device__ float g_rstd[BATCH * NGRP];
__device__ float g_svec[BATCH * CCH];                      // per-channel row sums of xn
__device__ float g_Gp[(size_t)KSPL * BATCH * CCH * CCH];   // K-split Gram partials (67MB)
__device__ float g_G[(size_t)BATCH * CCH * CCH];
__device__ float g_P[(size_t)BATCH * CCH * CCH];
__device__ float g_L[(size_t)BATCH * CCH * CCH];           // logits -> softmax in place
__device__ float g_M[(size_t)BATCH * CCH * CCH];
__device__ float g_We[(size_t)BATCH * CCH * CCH];
__device__ float g_u[BATCH * CCH];
__device__ float g_wv[BATCH * CCH];
__device__ float g_cv[BATCH * CCH];

// ---------------- packed f32x2 helpers -------------------------------------
__device__ __forceinline__ unsigned long long pack2(float lo, float hi) {
    unsigned long long r;
    asm("mov.b64 %0, {%1, %2};" : "=l"(r) : "f"(lo), "f"(hi));
    return r;
}
__device__ __forceinline__ void unpack2(unsigned long long v, float &lo, float &hi) {
    asm("mov.b64 {%0, %1}, %2;" : "=f"(lo), "=f"(hi) : "l"(v));
}
__device__ __forceinline__ void ffma2(unsigned long long &d, unsigned long long a,
                                      unsigned long long b) {
    asm("fma.rn.f32x2 %0, %1, %2, %3;" : "=l"(d) : "l"(a), "l"(b), "l"(d));
}

// ---------------- GroupNorm stage 1: per-channel sums ----------------------
__global__ void k_chansum(const float* __restrict__ x) {
    int bc = blockIdx.x;                       // b*512 + c
    const float4* row = (const float4*)(x + (size_t)bc * NSP);
    float s = 0.f, sq = 0.f;
    for (int i = threadIdx.x; i < NSP / 4; i += blockDim.x) {
        float4 v = row[i];
        s  += v.x + v.y + v.z + v.w;
        sq += v.x * v.x + v.y * v.y + v.z * v.z + v.w * v.w;
    }
    __shared__ float ss[256], ssq[256];
    ss[threadIdx.x] = s; ssq[threadIdx.x] = sq;
    __syncthreads();
    for (int st = 128; st > 0; st >>= 1) {
        if (threadIdx.x < st) {
            ss[threadIdx.x]  += ss[threadIdx.x + st];
            ssq[threadIdx.x] += ssq[threadIdx.x + st];
        }
        __syncthreads();
    }
    if (threadIdx.x == 0) { g_chansum[bc] = ss[0]; g_chansq[bc] = ssq[0]; }
}

// ---------------- GroupNorm stage 2: group stats + channel row-sums --------
__global__ void k_stats(const float* __restrict__ gn_w, const float* __restrict__ gn_b) {
    __shared__ float sm[BATCH * NGRP], sr[BATCH * NGRP];
    int t = threadIdx.x;
    if (t < BATCH * NGRP) {
        float s = 0.f, sq = 0.f;
        for (int c = 0; c < CPG; c++) { s += g_chansum[t * CPG + c]; sq += g_chansq[t * CPG + c]; }
        float inv  = 1.f / ((float)CPG * (float)NSP);
        float mean = s * inv;
        float var  = sq * inv - mean * mean;
        float rstd = rsqrtf(var + EPSV);
        g_mean[t] = mean; g_rstd[t] = rstd;
        sm[t] = mean; sr[t] = rstd;
    }
    __syncthreads();
    for (int bc = t; bc < BATCH * CCH; bc += blockDim.x) {
        int grp = bc / CPG;
        int c   = bc % CCH;
        float sv = (g_chansum[bc] - (float)NSP * sm[grp]) * sr[grp] * gn_w[c]
                 + (float)NSP * gn_b[c];
        g_svec[bc] = sv;
    }
}

// ---------------- GroupNorm stage 3: write xn -------------------------------
__global__ void k_xn(const float* __restrict__ x, const float* __restrict__ gn_w,
                     const float* __restrict__ gn_b) {
    int bc  = blockIdx.x;
    int grp = bc / CPG;
    int c   = bc % CCH;
    float a  = g_rstd[grp] * gn_w[c];
    float bb = gn_b[c] - g_mean[grp] * a;
    const float4* src = (const float4*)(x + (size_t)bc * NSP);
    float4* dst = (float4*)(g_xn + (size_t)bc * NSP);
    for (int i = threadIdx.x; i < NSP / 4; i += blockDim.x) {
        float4 v = src[i];
        v.x = v.x * a + bb; v.y = v.y * a + bb; v.z = v.z * a + bb; v.w = v.w * a + bb;
        dst[i] = v;
    }
}

// ---------------- Gram: G = xn @ xn^T, 128x128 tiles, 8x8/thread, K-split ---
__global__ void __launch_bounds__(256) k_gram() {
    int tri = blockIdx.x, ks = blockIdx.y, b = blockIdx.z;
    int bi = 0, rem = tri;
    while (rem >= 4 - bi) { rem -= 4 - bi; bi++; }
    int bj = bi + rem;

    const float* base = g_xn + (size_t)b * CCH * NSP;
    __shared__ __align__(16) float As[16][132];
    __shared__ __align__(16) float Bs[16][132];
    int tid = threadIdx.x;
    // load mapping: 128 rows x 16 k, 2x float4 per thread
    int lr = tid >> 1;                 // 0..127
    int lc = (tid & 1) << 3;           // 0 or 8
    // compute mapping: 8x8 outputs
    int ty = tid >> 4, tx = tid & 15;  // row = ty*8, col = tx*8
    const int KCH = NSP / KSPL;        // 1024

    const float* aptr = base + (size_t)(bi * 128 + lr) * NSP + ks * KCH + lc;
    const float* bptr = base + (size_t)(bj * 128 + lr) * NSP + ks * KCH + lc;

    unsigned long long acc[8][4];
#pragma unroll
    for (int i = 0; i < 8; i++)
#pragma unroll
        for (int j = 0; j < 4; j++) acc[i][j] = 0ull;

    float4 av0 = *(const float4*)aptr;
    float4 av1 = *(const float4*)(aptr + 4);
    float4 bv0 = *(const float4*)bptr;
    float4 bv1 = *(const float4*)(bptr + 4);

    for (int k0 = 0; k0 < KCH; k0 += 16) {
        __syncthreads();
        As[lc + 0][lr] = av0.x; As[lc + 1][lr] = av0.y; As[lc + 2][lr] = av0.z; As[lc + 3][lr] = av0.w;
        As[lc + 4][lr] = av1.x; As[lc + 5][lr] = av1.y; As[lc + 6][lr] = av1.z; As[lc + 7][lr] = av1.w;
        Bs[lc + 0][lr] = bv0.x; Bs[lc + 1][lr] = bv0.y; Bs[lc + 2][lr] = bv0.z; Bs[lc + 3][lr] = bv0.w;
        Bs[lc + 4][lr] = bv1.x; Bs[lc + 5][lr] = bv1.y; Bs[lc + 6][lr] = bv1.z; Bs[lc + 7][lr] = bv1.w;
        __syncthreads();
        if (k0 + 16 < KCH) {
            av0 = *(const float4*)(aptr + k0 + 16);
            av1 = *(const float4*)(aptr + k0 + 20);
            bv0 = *(const float4*)(bptr + k0 + 16);
            bv1 = *(const float4*)(bptr + k0 + 20);
        }
#pragma unroll
        for (int kk = 0; kk < 16; kk++) {
            float4 a0 = *(const float4*)&As[kk][ty << 3];
            float4 a1 = *(const float4*)&As[kk][(ty << 3) + 4];
            unsigned long long ap[8];
            ap[0] = pack2(a0.x, a0.x); ap[1] = pack2(a0.y, a0.y);
            ap[2] = pack2(a0.z, a0.z); ap[3] = pack2(a0.w, a0.w);
            ap[4] = pack2(a1.x, a1.x); ap[5] = pack2(a1.y, a1.y);
            ap[6] = pack2(a1.z, a1.z); ap[7] = pack2(a1.w, a1.w);
            ulonglong2 q0 = *(const ulonglong2*)&Bs[kk][tx << 3];
            ulonglong2 q1 = *(const ulonglong2*)&Bs[kk][(tx << 3) + 4];
#pragma unroll
            for (int i = 0; i < 8; i++) {
                ffma2(acc[i][0], ap[i], q0.x);
                ffma2(acc[i][1], ap[i], q0.y);
                ffma2(acc[i][2], ap[i], q1.x);
                ffma2(acc[i][3], ap[i], q1.y);
            }
        }
    }

    float* Gp = g_Gp + ((size_t)ks * BATCH + b) * CCH * CCH;
    int gi0 = bi * 128 + (ty << 3);
    int gj0 = bj * 128 + (tx << 3);
#pragma unroll
    for (int i = 0; i < 8; i++) {
        int gi = gi0 + i;
#pragma unroll
        for (int jp = 0; jp < 4; jp++) {
            float lo, hi; unpack2(acc[i][jp], lo, hi);
            int gj = gj0 + (jp << 1);
            Gp[(size_t)gi * CCH + gj]     = lo;
            Gp[(size_t)gi * CCH + gj + 1] = hi;
            if (bi != bj) {
                Gp[(size_t)gj * CCH + gi]       = lo;
                Gp[(size_t)(gj + 1) * CCH + gi] = hi;
            }
        }
    }
}

// ---------------- reduce K-split Gram partials ------------------------------
__global__ void k_gsum() {
    size_t i = (size_t)blockIdx.x * blockDim.x + threadIdx.x;   // < BATCH*CCH*CCH
    const size_t stride = (size_t)BATCH * CCH * CCH;
    float s = 0.f;
#pragma unroll
    for (int p = 0; p < KSPL; p++) s += g_Gp[i + (size_t)p * stride];
    g_G[i] = s;
}

// ---------------- u = Wq@s, w = Wk@s ----------------------------------------
__global__ void k_uv(const float* __restrict__ qkv_w) {
    int idx = blockIdx.x * blockDim.x + threadIdx.x;   // 0..2047
    int b     = idx >> 10;
    int which = (idx >> 9) & 1;
    int row   = idx & 511;
    const float* W = qkv_w + (size_t)(which * CCH + row) * CCH;
    const float* s = g_svec + b * CCH;
    float acc = 0.f;
    for (int c = 0; c < CCH; c++) acc += W[c] * s[c];
    if (which == 0) g_u[b * CCH + row] = acc; else g_wv[b * CCH + row] = acc;
}

// ---------------- generic small NN GEMM: 3 uses ------------------------------
__global__ void __launch_bounds__(256) k_small_nn(int mode, const float* __restrict__ qkv_w,
                                                  const float* __restrict__ proj_w) {
    int bjt = blockIdx.x, bit = blockIdx.y, b = blockIdx.z;
    const float *A, *B; float* C;
    if (mode == 0)      { A = qkv_w;                         B = g_G + (size_t)b * CCH * CCH; C = g_P  + (size_t)b * CCH * CCH; }
    else if (mode == 1) { A = proj_w;                        B = g_L + (size_t)b * CCH * CCH; C = g_M  + (size_t)b * CCH * CCH; }
    else                { A = g_M + (size_t)b * CCH * CCH;   B = qkv_w + (size_t)1024 * CCH;  C = g_We + (size_t)b * CCH * CCH; }

    __shared__ __align__(16) float As[16][68];
    __shared__ __align__(16) float Bs[16][64];
    int tid = threadIdx.x, ty = tid >> 4, tx = tid & 15;
    int alr = tid >> 2, alc = (tid & 3) << 2;
    int br = tid >> 4, bc = (tid & 15) << 2;
    const float* aptr = A + (size_t)(bit * 64 + alr) * CCH + alc;
    const float* bptr = B + (size_t)br * CCH + bjt * 64 + bc;

    float acc[4][4] = {};
    for (int k0 = 0; k0 < CCH; k0 += 16) {
        float4 av = *(const float4*)(aptr + k0);
        float4 bv = *(const float4*)(bptr + (size_t)k0 * CCH);
        __syncthreads();
        As[alc + 0][alr] = av.x; As[alc + 1][alr] = av.y;
        As[alc + 2][alr] = av.z; As[alc + 3][alr] = av.w;
        *(float4*)&Bs[br][bc] = bv;
        __syncthreads();
#pragma unroll
        for (int kk = 0; kk < 16; kk++) {
            float4 a  = *(const float4*)&As[kk][ty << 2];
            float4 bb = *(const float4*)&Bs[kk][tx << 2];
            acc[0][0] += a.x * bb.x; acc[0][1] += a.x * bb.y; acc[0][2] += a.x * bb.z; acc[0][3] += a.x * bb.w;
            acc[1][0] += a.y * bb.x; acc[1][1] += a.y * bb.y; acc[1][2] += a.y * bb.z; acc[1][3] += a.y * bb.w;
            acc[2][0] += a.z * bb.x; acc[2][1] += a.z * bb.y; acc[2][2] += a.z * bb.z; acc[2][3] += a.z * bb.w;
            acc[3][0] += a.w * bb.x; acc[3][1] += a.w * bb.y; acc[3][2] += a.w * bb.z; acc[3][3] += a.w * bb.w;
        }
    }
    int gi0 = bit * 64 + (ty << 2), gj0 = bjt * 64 + (tx << 2);
#pragma unroll
    for (int i = 0; i < 4; i++)
#pragma unroll
        for (int j = 0; j < 4; j++)
            C[(size_t)(gi0 + i) * CCH + gj0 + j] = acc[i][j];
}

// ---------------- logits: L = scale*(P@Wk^T + rank-1 bias terms) ------------
__global__ void __launch_bounds__(256) k_nt_logits(const float* __restrict__ qkv_w,
                                                   const float* __restrict__ qkv_b) {
    int bjt = blockIdx.x, bit = blockIdx.y, b = blockIdx.z;
    const float* A  = g_P + (size_t)b * CCH * CCH;
    const float* Bm = qkv_w + (size_t)CCH * CCH;   // Wk rows
    __shared__ __align__(16) float As[16][68];
    __shared__ __align__(16) float Bs[16][68];
    int tid = threadIdx.x, ty = tid >> 4, tx = tid & 15;
    int lr = tid >> 2, lc = (tid & 3) << 2;
    const float* aptr = A  + (size_t)(bit * 64 + lr) * CCH + lc;
    const float* bptr = Bm + (size_t)(bjt * 64 + lr) * CCH + lc;

    float acc[4][4] = {};
    for (int k0 = 0; k0 < CCH; k0 += 16) {
        float4 av = *(const float4*)(aptr + k0);
        float4 bv = *(const float4*)(bptr + k0);
        __syncthreads();
        As[lc + 0][lr] = av.x; As[lc + 1][lr] = av.y; As[lc + 2][lr] = av.z; As[lc + 3][lr] = av.w;
        Bs[lc + 0][lr] = bv.x; Bs[lc + 1][lr] = bv.y; Bs[lc + 2][lr] = bv.z; Bs[lc + 3][lr] = bv.w;
        __syncthreads();
#pragma unroll
        for (int kk = 0; kk < 16; kk++) {
            float4 a  = *(const float4*)&As[kk][ty << 2];
            float4 bb = *(const float4*)&Bs[kk][tx << 2];
            acc[0][0] += a.x * bb.x; acc[0][1] += a.x * bb.y; acc[0][2] += a.x * bb.z; acc[0][3] += a.x * bb.w;
            acc[1][0] += a.y * bb.x; acc[1][1] += a.y * bb.y; acc[1][2] += a.y * bb.z; acc[1][3] += a.y * bb.w;
            acc[2][0] += a.z * bb.x; acc[2][1] += a.z * bb.y; acc[2][2] += a.z * bb.z; acc[2][3] += a.z * bb.w;
            acc[3][0] += a.w * bb.x; acc[3][1] += a.w * bb.y; acc[3][2] += a.w * bb.z; acc[3][3] += a.w * bb.w;
        }
    }
    const float scale = 0.04419417382415922f;   // 1/sqrt(512)
    const float* u = g_u  + b * CCH;
    const float* w = g_wv + b * CCH;
    float* L = g_L + (size_t)b * CCH * CCH;
    int gi0 = bit * 64 + (ty << 2), gj0 = bjt * 64 + (tx << 2);
#pragma unroll
    for (int i = 0; i < 4; i++) {
        int gi = gi0 + i;
        float bq = qkv_b[gi];
        float ui = u[gi];
#pragma unroll
        for (int j = 0; j < 4; j++) {
            int gj = gj0 + j;
            float bk = qkv_b[CCH + gj];
            float val = acc[i][j] + bq * w[gj] + bk * ui + (float)NSP * bq * bk;
            L[(size_t)gi * CCH + gj] = val * scale;
        }
    }
}

// ---------------- softmax over last dim of L (in place) ---------------------
__global__ void k_softmax() {
    int row = blockIdx.x;                        // b*512 + i
    float* L = g_L + (size_t)row * CCH;
    __shared__ float red[256];
    int t = threadIdx.x;
    float v0 = L[t], v1 = L[t + 256];
    red[t] = fmaxf(v0, v1);
    __syncthreads();
    for (int st = 128; st > 0; st >>= 1) {
        if (t < st) red[t] = fmaxf(red[t], red[t + st]);
        __syncthreads();
    }
    float mx = red[0];
    __syncthreads();
    float e0 = expf(v0 - mx), e1 = expf(v1 - mx);
    red[t] = e0 + e1;
    __syncthreads();
    for (int st = 128; st > 0; st >>= 1) {
        if (t < st) red[t] += red[t + st];
        __syncthreads();
    }
    float inv = 1.f / red[0];
    L[t] = e0 * inv; L[t + 256] = e1 * inv;
}

// ---------------- cv = M @ bv + proj_b ---------------------------------------
__global__ void k_cv(const float* __restrict__ qkv_b, const float* __restrict__ proj_b) {
    int idx = blockIdx.x * blockDim.x + threadIdx.x;   // 0..1023
    int b = idx >> 9, o = idx & 511;
    const float* M = g_M + (size_t)b * CCH * CCH + (size_t)o * CCH;
    float acc = proj_b[o];
    for (int d = 0; d < CCH; d++) acc += M[d] * qkv_b[1024 + d];
    g_cv[idx] = acc;
}

// ---------------- final: out = x + We @ xn + cv, 128x128 tiles, 8x8/thread ---
__global__ void __launch_bounds__(256) k_final(const float* __restrict__ x,
                                               float* __restrict__ out) {
    int bn = blockIdx.x, bo = blockIdx.y, b = blockIdx.z;   // bo in 0..3 (CCH/128)
    const float* A = g_We + (size_t)b * CCH * CCH;
    const float* B = g_xn + (size_t)b * CCH * NSP;
    __shared__ __align__(16) float As[16][132];
    __shared__ __align__(16) float Bs[16][132];
    int tid = threadIdx.x;
    // A load: 128 rows x 16 k (transposed into As[k][m])
    int alr = tid >> 1;               // 0..127
    int alc = (tid & 1) << 3;         // 0 or 8
    // B load: 16 k-rows x 128 n
    int bkr = tid >> 4;               // 0..15
    int bnc = (tid & 15) << 3;        // 0..120
    // compute: 8x8 per thread
    int ty = tid >> 4, tx = tid & 15;

    const float* aptr = A + (size_t)(bo * 128 + alr) * CCH + alc;
    const float* bptr = B + (size_t)bkr * NSP + bn * 128 + bnc;

    unsigned long long acc[8][4];
#pragma unroll
    for (int i = 0; i < 8; i++)
#pragma unroll
        for (int j = 0; j < 4; j++) acc[i][j] = 0ull;

    float4 av0 = *(const float4*)aptr;
    float4 av1 = *(const float4*)(aptr + 4);
    float4 bv0 = *(const float4*)bptr;
    float4 bv1 = *(const float4*)(bptr + 4);

    for (int k0 = 0; k0 < CCH; k0 += 16) {
        __syncthreads();
        As[alc + 0][alr] = av0.x; As[alc + 1][alr] = av0.y; As[alc + 2][alr] = av0.z; As[alc + 3][alr] = av0.w;
        As[alc + 4][alr] = av1.x; As[alc + 5][alr] = av1.y; As[alc + 6][alr] = av1.z; As[alc + 7][alr] = av1.w;
        *(float4*)&Bs[bkr][bnc]     = bv0;
        *(float4*)&Bs[bkr][bnc + 4] = bv1;
        __syncthreads();
        if (k0 + 16 < CCH) {
            av0 = *(const float4*)(aptr + k0 + 16);
            av1 = *(const float4*)(aptr + k0 + 20);
            const float* nb = bptr + (size_t)(k0 + 16) * NSP;
            bv0 = *(const float4*)nb;
            bv1 = *(const float4*)(nb + 4);
        }
#pragma unroll
        for (int kk = 0; kk < 16; kk++) {
            float4 a0 = *(const float4*)&As[kk][ty << 3];
            float4 a1 = *(const float4*)&As[kk][(ty << 3) + 4];
            unsigned long long ap[8];
            ap[0] = pack2(a0.x, a0.x); ap[1] = pack2(a0.y, a0.y);
            ap[2] = pack2(a0.z, a0.z); ap[3] = pack2(a0.w, a0.w);
            ap[4] = pack2(a1.x, a1.x); ap[5] = pack2(a1.y, a1.y);
            ap[6] = pack2(a1.z, a1.z); ap[7] = pack2(a1.w, a1.w);
            ulonglong2 q0 = *(const ulonglong2*)&Bs[kk][tx << 3];
            ulonglong2 q1 = *(const ulonglong2*)&Bs[kk][(tx << 3) + 4];
#pragma unroll
            for (int i = 0; i < 8; i++) {
                ffma2(acc[i][0], ap[i], q0.x);
                ffma2(acc[i][1], ap[i], q0.y);
                ffma2(acc[i][2], ap[i], q1.x);
                ffma2(acc[i][3], ap[i], q1.y);
            }
        }
    }

    int gi0 = bo * 128 + (ty << 3);
    int n0  = bn * 128 + (tx << 3);
    const float* cvp = g_cv + b * CCH;
#pragma unroll
    for (int i = 0; i < 8; i++) {
        int gi = gi0 + i;
        float cadd = cvp[gi];
        size_t off = ((size_t)b * CCH + gi) * NSP + n0;
        float4 x0 = *(const float4*)(x + off);
        float4 x1 = *(const float4*)(x + off + 4);
        float l0, h0, l1, h1, l2, h2, l3, h3;
        unpack2(acc[i][0], l0, h0); unpack2(acc[i][1], l1, h1);
        unpack2(acc[i][2], l2, h2); unpack2(acc[i][3], l3, h3);
        float4 o0 = make_float4(x0.x + l0 + cadd, x0.y + h0 + cadd,
                                x0.z + l1 + cadd, x0.w + h1 + cadd);
        float4 o1 = make_float4(x1.x + l2 + cadd, x1.y + h2 + cadd,
                                x1.z + l3 + cadd, x1.w + h3 + cadd);
        *(float4*)(out + off)     = o0;
        *(float4*)(out + off + 4) = o1;
    }
}

// ---------------- launch ------------------------------------------------------
extern "C" void kernel_launch(void* const* d_in, const int* in_sizes, int n_in,
                              void* d_out, int out_size) {
    const float* x      = (const float*)d_in[0];
    const float* gn_w   = (const float*)d_in[1];
    const float* gn_b   = (const float*)d_in[2];
    const float* qkv_w  = (const float*)d_in[3];
    const float* qkv_b  = (const float*)d_in[4];
    const float* proj_w = (const float*)d_in[5];
    const float* proj_b = (const float*)d_in[6];
    float* out = (float*)d_out;

    k_chansum<<<BATCH * CCH, 256>>>(x);
    k_stats<<<1, 256>>>(gn_w, gn_b);
    k_xn<<<BATCH * CCH, 256>>>(x, gn_w, gn_b);
    k_gram<<<dim3(10, KSPL, BATCH), 256>>>();
    k_gsum<<<(BATCH * CCH * CCH) / 256, 256>>>();
    k_uv<<<8, 256>>>(qkv_w);
    k_small_nn<<<dim3(8, 8, BATCH), 256>>>(0, qkv_w, proj_w);   // P = Wq @ G
    k_nt_logits<<<dim3(8, 8, BATCH), 256>>>(qkv_w, qkv_b);      // L = scale*(P@Wk^T + bias)
    k_softmax<<<BATCH * CCH, 256>>>();                           // A = softmax(L)
    k_small_nn<<<dim3(8, 8, BATCH), 256>>>(1, qkv_w, proj_w);   // M = proj_w @ A
    k_small_nn<<<dim3(8, 8, BATCH), 256>>>(2, qkv_w, proj_w);   // We = M @ Wv
    k_cv<<<4, 256>>>(qkv_b, proj_b);
    k_final<<<dim3(NSP / 128, CCH / 128, BATCH), 256>>>(x, out); // out = x + We@xn + cv
}

// round 5
// speedup vs baseline: 2.0376x; 1.6718x over previous
#include <cuda_runtime.h>
#include <cuda_bf16.h>
#include <cstdint>

#define BATCH 2
#define CCH   512
#define NGRP  32
#define CPG   16
#define NSP   32768
#define EPSV  1e-5f
#define KSPL  16
#define GKC   32

// ---------------- scratch (device globals; no runtime allocation) ----------
__device__ float g_chansum[BATCH * CCH];
__device__ float g_chansq[BATCH * CCH];
__device__ float g_mean[BATCH * NGRP];
__device__ float g_rstd[BATCH * NGRP];
__device__ float g_alpha[BATCH * CCH];
__device__ float g_beta[BATCH * CCH];
__device__ float g_svec[BATCH * CCH];
__device__ float g_Gp[(size_t)KSPL * BATCH * CCH * CCH];   // raw-x Gram partials
__device__ float g_G[(size_t)BATCH * CCH * CCH];
__device__ float g_P[(size_t)BATCH * CCH * CCH];
__device__ float g_L[(size_t)BATCH * CCH * CCH];
__device__ float g_M[(size_t)BATCH * CCH * CCH];
__device__ float g_We[(size_t)BATCH * CCH * CCH];
__device__ float g_u[BATCH * CCH];
__device__ float g_wv[BATCH * CCH];
__device__ float g_cv[BATCH * CCH];

// ---------------- mma / ldmatrix helpers -------------------------------------
__device__ __forceinline__ uint32_t smem_u32(const void* p) {
    return (uint32_t)__cvta_generic_to_shared(p);
}
__device__ __forceinline__ void mma_bf16(float* c, const uint32_t* a, const uint32_t* b) {
    asm volatile(
        "mma.sync.aligned.m16n8k16.row.col.f32.bf16.bf16.f32 "
        "{%0,%1,%2,%3}, {%4,%5,%6,%7}, {%8,%9}, {%0,%1,%2,%3};\n"
        : "+f"(c[0]), "+f"(c[1]), "+f"(c[2]), "+f"(c[3])
        : "r"(a[0]), "r"(a[1]), "r"(a[2]), "r"(a[3]), "r"(b[0]), "r"(b[1]));
}
__device__ __forceinline__ void ldsm_x4(uint32_t* r, uint32_t addr) {
    asm volatile("ldmatrix.sync.aligned.m8n8.x4.shared.b16 {%0,%1,%2,%3}, [%4];"
                 : "=r"(r[0]), "=r"(r[1]), "=r"(r[2]), "=r"(r[3]) : "r"(addr));
}
__device__ __forceinline__ void ldsm_x4_t(uint32_t* r, uint32_t addr) {
    asm volatile("ldmatrix.sync.aligned.m8n8.x4.trans.shared.b16 {%0,%1,%2,%3}, [%4];"
                 : "=r"(r[0]), "=r"(r[1]), "=r"(r[2]), "=r"(r[3]) : "r"(addr));
}
__device__ __forceinline__ uint4 pack8_hi(const float* v) {
    uint4 u; uint32_t* p = (uint32_t*)&u;
#pragma unroll
    for (int j = 0; j < 4; j++) {
        __nv_bfloat162 t = __halves2bfloat162(__float2bfloat16(v[2 * j]),
                                              __float2bfloat16(v[2 * j + 1]));
        p[j] = *(uint32_t*)&t;
    }
    return u;
}
__device__ __forceinline__ uint4 pack8_lo(const float* v) {
    uint4 u; uint32_t* p = (uint32_t*)&u;
#pragma unroll
    for (int j = 0; j < 4; j++) {
        float a = v[2 * j], b = v[2 * j + 1];
        __nv_bfloat16 ha = __float2bfloat16(a), hb = __float2bfloat16(b);
        __nv_bfloat162 t = __halves2bfloat162(
            __float2bfloat16(a - __bfloat162float(ha)),
            __float2bfloat16(b - __bfloat162float(hb)));
        p[j] = *(uint32_t*)&t;
    }
    return u;
}

// ---------------- GroupNorm stage 1: per-channel sums ----------------------
__global__ void k_chansum(const float* __restrict__ x) {
    int bc = blockIdx.x;
    const float4* row = (const float4*)(x + (size_t)bc * NSP);
    float s = 0.f, sq = 0.f;
    for (int i = threadIdx.x; i < NSP / 4; i += blockDim.x) {
        float4 v = row[i];
        s  += v.x + v.y + v.z + v.w;
        sq += v.x * v.x + v.y * v.y + v.z * v.z + v.w * v.w;
    }
    __shared__ float ss[256], ssq[256];
    ss[threadIdx.x] = s; ssq[threadIdx.x] = sq;
    __syncthreads();
    for (int st = 128; st > 0; st >>= 1) {
        if (threadIdx.x < st) {
            ss[threadIdx.x]  += ss[threadIdx.x + st];
            ssq[threadIdx.x] += ssq[threadIdx.x + st];
        }
        __syncthreads();
    }
    if (threadIdx.x == 0) { g_chansum[bc] = ss[0]; g_chansq[bc] = ssq[0]; }
}

// ---------------- GroupNorm stage 2: stats + alpha/beta + svec ---------------
__global__ void k_stats(const float* __restrict__ gn_w, const float* __restrict__ gn_b) {
    __shared__ float sm[BATCH * NGRP], sr[BATCH * NGRP];
    int t = threadIdx.x;
    if (t < BATCH * NGRP) {
        float s = 0.f, sq = 0.f;
        for (int c = 0; c < CPG; c++) { s += g_chansum[t * CPG + c]; sq += g_chansq[t * CPG + c]; }
        float inv  = 1.f / ((float)CPG * (float)NSP);
        float mean = s * inv;
        float var  = sq * inv - mean * mean;
        float rstd = rsqrtf(var + EPSV);
        g_mean[t] = mean; g_rstd[t] = rstd;
        sm[t] = mean; sr[t] = rstd;
    }
    __syncthreads();
    for (int bc = t; bc < BATCH * CCH; bc += blockDim.x) {
        int grp = bc / CPG;
        int c   = bc % CCH;
        float a  = sr[grp] * gn_w[c];
        float be = gn_b[c] - sm[grp] * a;
        g_alpha[bc] = a;
        g_beta[bc]  = be;
        g_svec[bc]  = a * g_chansum[bc] + (float)NSP * be;
    }
}

// ---------------- raw-x Gram via HMMA (hi/lo bf16 split) --------------------
__global__ void __launch_bounds__(256) k_gram_mma(const float* __restrict__ x) {
    __shared__ __align__(16) __nv_bfloat16 sAh[128 * 40], sAl[128 * 40];
    __shared__ __align__(16) __nv_bfloat16 sBh[128 * 40], sBl[128 * 40];

    int tid = threadIdx.x, lane = tid & 31, wid = tid >> 5;
    int tri = blockIdx.x, ks = blockIdx.y, b = blockIdx.z;
    int bi = 0, rem = tri;
    while (rem >= 4 - bi) { rem -= 4 - bi; bi++; }
    int bj = bi + rem;
    bool diag = (bi == bj);

    int lr = tid >> 1;
    int lc = (tid & 1) << 4;
    const float* aRow = x + ((size_t)b * CCH + bi * 128 + lr) * NSP;
    const float* bRow = x + ((size_t)b * CCH + bj * 128 + lr) * NSP;
    const int kbase = ks * (NSP / KSPL);
    const int NCH = (NSP / KSPL) / GKC;   // 64

    float av[16], bv[16];
#pragma unroll
    for (int q = 0; q < 4; q++) {
        *(float4*)&av[4 * q] = *(const float4*)(aRow + kbase + lc + 4 * q);
        if (!diag) *(float4*)&bv[4 * q] = *(const float4*)(bRow + kbase + lc + 4 * q);
    }

    float acc[2][8][4];
#pragma unroll
    for (int i = 0; i < 2; i++)
#pragma unroll
        for (int j = 0; j < 8; j++)
#pragma unroll
            for (int k = 0; k < 4; k++) acc[i][j][k] = 0.f;

    int wm = (wid & 3) * 32, wn = (wid >> 2) * 64;
    uint32_t aoff[2], boff[4];
#pragma unroll
    for (int mt = 0; mt < 2; mt++)
        aoff[mt] = ((wm + mt * 16 + (lane & 15)) * 40 + ((lane >> 4) << 3)) * 2;
#pragma unroll
    for (int np = 0; np < 4; np++)
        boff[np] = ((wn + np * 16 + (lane & 7) + ((lane >> 4) & 1) * 8) * 40 +
                    (((lane >> 3) & 1) << 3)) * 2;

    uint32_t sAhA = smem_u32(sAh), sAlA = smem_u32(sAl);
    uint32_t sBhA = diag ? sAhA : smem_u32(sBh);
    uint32_t sBlA = diag ? sAlA : smem_u32(sBl);
    uint32_t soff = (lr * 40 + lc) * 2;

    for (int ch = 0; ch < NCH; ch++) {
        __syncthreads();
        *(uint4*)((char*)sAh + soff)      = pack8_hi(av);
        *(uint4*)((char*)sAh + soff + 16) = pack8_hi(av + 8);
        *(uint4*)((char*)sAl + soff)      = pack8_lo(av);
        *(uint4*)((char*)sAl + soff + 16) = pack8_lo(av + 8);
        if (!diag) {
            *(uint4*)((char*)sBh + soff)      = pack8_hi(bv);
            *(uint4*)((char*)sBh + soff + 16) = pack8_hi(bv + 8);
            *(uint4*)((char*)sBl + soff)      = pack8_lo(bv);
            *(uint4*)((char*)sBl + soff + 16) = pack8_lo(bv + 8);
        }
        __syncthreads();
        if (ch + 1 < NCH) {
            int kb = kbase + (ch + 1) * GKC;
#pragma unroll
            for (int q = 0; q < 4; q++) {
                *(float4*)&av[4 * q] = *(const float4*)(aRow + kb + lc + 4 * q);
                if (!diag) *(float4*)&bv[4 * q] = *(const float4*)(bRow + kb + lc + 4 * q);
            }
        }
#pragma unroll
        for (int k0 = 0; k0 < GKC; k0 += 16) {
            uint32_t ah[2][4], al[2][4];
#pragma unroll
            for (int mt = 0; mt < 2; mt++) {
                ldsm_x4(ah[mt], sAhA + aoff[mt] + k0 * 2);
                ldsm_x4(al[mt], sAlA + aoff[mt] + k0 * 2);
            }
            uint32_t bh[8][2], bl[8][2];
#pragma unroll
            for (int np = 0; np < 4; np++) {
                uint32_t r[4];
                ldsm_x4(r, sBhA + boff[np] + k0 * 2);
                bh[2 * np][0] = r[0]; bh[2 * np][1] = r[1];
                bh[2 * np + 1][0] = r[2]; bh[2 * np + 1][1] = r[3];
                ldsm_x4(r, sBlA + boff[np] + k0 * 2);
                bl[2 * np][0] = r[0]; bl[2 * np][1] = r[1];
                bl[2 * np + 1][0] = r[2]; bl[2 * np + 1][1] = r[3];
            }
#pragma unroll
            for (int mt = 0; mt < 2; mt++)
#pragma unroll
                for (int nt = 0; nt < 8; nt++) {
                    mma_bf16(acc[mt][nt], ah[mt], bh[nt]);
                    mma_bf16(acc[mt][nt], ah[mt], bl[nt]);
                    mma_bf16(acc[mt][nt], al[mt], bh[nt]);
                }
        }
    }

    float* Gp = g_Gp + ((size_t)ks * BATCH + b) * CCH * CCH;
    int g = lane >> 2, c2 = (lane & 3) << 1;
#pragma unroll
    for (int mt = 0; mt < 2; mt++)
#pragma unroll
        for (int nt = 0; nt < 8; nt++) {
            int gi = bi * 128 + wm + mt * 16 + g;
            int gj = bj * 128 + wn + nt * 8 + c2;
            float* p = acc[mt][nt];
            Gp[(size_t)gi * CCH + gj]           = p[0];
            Gp[(size_t)gi * CCH + gj + 1]       = p[1];
            Gp[(size_t)(gi + 8) * CCH + gj]     = p[2];
            Gp[(size_t)(gi + 8) * CCH + gj + 1] = p[3];
            if (!diag) {
                Gp[(size_t)gj * CCH + gi]           = p[0];
                Gp[(size_t)(gj + 1) * CCH + gi]     = p[1];
                Gp[(size_t)gj * CCH + gi + 8]       = p[2];
                Gp[(size_t)(gj + 1) * CCH + gi + 8] = p[3];
            }
        }
}

// ---------------- reduce partials + GN rank-1 corrections -> xn Gram --------
__global__ void k_gsum() {
    size_t t = (size_t)blockIdx.x * blockDim.x + threadIdx.x;   // < BATCH*CCH*CCH
    int b = (int)(t / ((size_t)CCH * CCH));
    int rm = (int)(t % ((size_t)CCH * CCH));
    int i = rm / CCH, j = rm % CCH;
    const size_t stride = (size_t)BATCH * CCH * CCH;
    float s = 0.f;
#pragma unroll
    for (int p = 0; p < KSPL; p++) s += g_Gp[t + (size_t)p * stride];
    float ai = g_alpha[b * CCH + i], bi = g_beta[b * CCH + i];
    float aj = g_alpha[b * CCH + j], bj = g_beta[b * CCH + j];
    float Si = g_chansum[b * CCH + i], Sj = g_chansum[b * CCH + j];
    g_G[t] = ai * aj * s + ai * bj * Si + aj * bi * Sj + (float)NSP * bi * bj;
}

// ---------------- u = Wq@s, w = Wk@s ----------------------------------------
__global__ void k_uv(const float* __restrict__ qkv_w) {
    int idx = blockIdx.x * blockDim.x + threadIdx.x;
    int b     = idx >> 10;
    int which = (idx >> 9) & 1;
    int row   = idx & 511;
    const float* W = qkv_w + (size_t)(which * CCH + row) * CCH;
    const float* s = g_svec + b * CCH;
    float acc = 0.f;
    for (int c = 0; c < CCH; c++) acc += W[c] * s[c];
    if (which == 0) g_u[b * CCH + row] = acc; else g_wv[b * CCH + row] = acc;
}

// ---------------- generic small NN GEMM: 3 uses ------------------------------
__global__ void __launch_bounds__(256) k_small_nn(int mode, const float* __restrict__ qkv_w,
                                                  const float* __restrict__ proj_w) {
    int bjt = blockIdx.x, bit = blockIdx.y, b = blockIdx.z;
    const float *A, *B; float* C;
    if (mode == 0)      { A = qkv_w;                         B = g_G + (size_t)b * CCH * CCH; C = g_P  + (size_t)b * CCH * CCH; }
    else if (mode == 1) { A = proj_w;                        B = g_L + (size_t)b * CCH * CCH; C = g_M  + (size_t)b * CCH * CCH; }
    else                { A = g_M + (size_t)b * CCH * CCH;   B = qkv_w + (size_t)1024 * CCH;  C = g_We + (size_t)b * CCH * CCH; }

    __shared__ __align__(16) float As[16][68];
    __shared__ __align__(16) float Bs[16][64];
    int tid = threadIdx.x, ty = tid >> 4, tx = tid & 15;
    int alr = tid >> 2, alc = (tid & 3) << 2;
    int br = tid >> 4, bc = (tid & 15) << 2;
    const float* aptr = A + (size_t)(bit * 64 + alr) * CCH + alc;
    const float* bptr = B + (size_t)br * CCH + bjt * 64 + bc;

    float acc[4][4] = {};
    for (int k0 = 0; k0 < CCH; k0 += 16) {
        float4 av = *(const float4*)(aptr + k0);
        float4 bv = *(const float4*)(bptr + (size_t)k0 * CCH);
        __syncthreads();
        As[alc + 0][alr] = av.x; As[alc + 1][alr] = av.y;
        As[alc + 2][alr] = av.z; As[alc + 3][alr] = av.w;
        *(float4*)&Bs[br][bc] = bv;
        __syncthreads();
#pragma unroll
        for (int kk = 0; kk < 16; kk++) {
            float4 a  = *(const float4*)&As[kk][ty << 2];
            float4 bb = *(const float4*)&Bs[kk][tx << 2];
            acc[0][0] += a.x * bb.x; acc[0][1] += a.x * bb.y; acc[0][2] += a.x * bb.z; acc[0][3] += a.x * bb.w;
            acc[1][0] += a.y * bb.x; acc[1][1] += a.y * bb.y; acc[1][2] += a.y * bb.z; acc[1][3] += a.y * bb.w;
            acc[2][0] += a.z * bb.x; acc[2][1] += a.z * bb.y; acc[2][2] += a.z * bb.z; acc[2][3] += a.z * bb.w;
            acc[3][0] += a.w * bb.x; acc[3][1] += a.w * bb.y; acc[3][2] += a.w * bb.z; acc[3][3] += a.w * bb.w;
        }
    }
    int gi0 = bit * 64 + (ty << 2), gj0 = bjt * 64 + (tx << 2);
#pragma unroll
    for (int i = 0; i < 4; i++)
#pragma unroll
        for (int j = 0; j < 4; j++)
            C[(size_t)(gi0 + i) * CCH + gj0 + j] = acc[i][j];
}

// ---------------- logits: L = scale*(P@Wk^T + rank-1 bias terms) ------------
__global__ void __launch_bounds__(256) k_nt_logits(const float* __restrict__ qkv_w,
                                                   const float* __restrict__ qkv_b) {
    int bjt = blockIdx.x, bit = blockIdx.y, b = blockIdx.z;
    const float* A  = g_P + (size_t)b * CCH * CCH;
    const float* Bm = qkv_w + (size_t)CCH * CCH;
    __shared__ __align__(16) float As[16][68];
    __shared__ __align__(16) float Bs[16][68];
    int tid = threadIdx.x, ty = tid >> 4, tx = tid & 15;
    int lr = tid >> 2, lc = (tid & 3) << 2;
    const float* aptr = A  + (size_t)(bit * 64 + lr) * CCH + lc;
    const float* bptr = Bm + (size_t)(bjt * 64 + lr) * CCH + lc;

    float acc[4][4] = {};
    for (int k0 = 0; k0 < CCH; k0 += 16) {
        float4 av = *(const float4*)(aptr + k0);
        float4 bv = *(const float4*)(bptr + k0);
        __syncthreads();
        As[lc + 0][lr] = av.x; As[lc + 1][lr] = av.y; As[lc + 2][lr] = av.z; As[lc + 3][lr] = av.w;
        Bs[lc + 0][lr] = bv.x; Bs[lc + 1][lr] = bv.y; Bs[lc + 2][lr] = bv.z; Bs[lc + 3][lr] = bv.w;
        __syncthreads();
#pragma unroll
        for (int kk = 0; kk < 16; kk++) {
            float4 a  = *(const float4*)&As[kk][ty << 2];
            float4 bb = *(const float4*)&Bs[kk][tx << 2];
            acc[0][0] += a.x * bb.x; acc[0][1] += a.x * bb.y; acc[0][2] += a.x * bb.z; acc[0][3] += a.x * bb.w;
            acc[1][0] += a.y * bb.x; acc[1][1] += a.y * bb.y; acc[1][2] += a.y * bb.z; acc[1][3] += a.y * bb.w;
            acc[2][0] += a.z * bb.x; acc[2][1] += a.z * bb.y; acc[2][2] += a.z * bb.z; acc[2][3] += a.z * bb.w;
            acc[3][0] += a.w * bb.x; acc[3][1] += a.w * bb.y; acc[3][2] += a.w * bb.z; acc[3][3] += a.w * bb.w;
        }
    }
    const float scale = 0.04419417382415922f;
    const float* u = g_u  + b * CCH;
    const float* w = g_wv + b * CCH;
    float* L = g_L + (size_t)b * CCH * CCH;
    int gi0 = bit * 64 + (ty << 2), gj0 = bjt * 64 + (tx << 2);
#pragma unroll
    for (int i = 0; i < 4; i++) {
        int gi = gi0 + i;
        float bq = qkv_b[gi];
        float ui = u[gi];
#pragma unroll
        for (int j = 0; j < 4; j++) {
            int gj = gj0 + j;
            float bk = qkv_b[CCH + gj];
            float val = acc[i][j] + bq * w[gj] + bk * ui + (float)NSP * bq * bk;
            L[(size_t)gi * CCH + gj] = val * scale;
        }
    }
}

// ---------------- softmax over last dim of L (in place) ---------------------
__global__ void k_softmax() {
    int row = blockIdx.x;
    float* L = g_L + (size_t)row * CCH;
    __shared__ float red[256];
    int t = threadIdx.x;
    float v0 = L[t], v1 = L[t + 256];
    red[t] = fmaxf(v0, v1);
    __syncthreads();
    for (int st = 128; st > 0; st >>= 1) {
        if (t < st) red[t] = fmaxf(red[t], red[t + st]);
        __syncthreads();
    }
    float mx = red[0];
    __syncthreads();
    float e0 = expf(v0 - mx), e1 = expf(v1 - mx);
    red[t] = e0 + e1;
    __syncthreads();
    for (int st = 128; st > 0; st >>= 1) {
        if (t < st) red[t] += red[t + st];
        __syncthreads();
    }
    float inv = 1.f / red[0];
    L[t] = e0 * inv; L[t + 256] = e1 * inv;
}

// ---------------- cv = M@bv + proj_b + We@beta --------------------------------
__global__ void k_cv(const float* __restrict__ qkv_b, const float* __restrict__ proj_b) {
    int idx = blockIdx.x * blockDim.x + threadIdx.x;   // 0..1023
    int b = idx >> 9, o = idx & 511;
    const float* M  = g_M  + (size_t)b * CCH * CCH + (size_t)o * CCH;
    const float* We = g_We + (size_t)b * CCH * CCH + (size_t)o * CCH;
    const float* be = g_beta + b * CCH;
    float acc = proj_b[o];
    for (int d = 0; d < CCH; d++) acc += M[d] * qkv_b[1024 + d];
    for (int k = 0; k < CCH; k++) acc += We[k] * be[k];
    g_cv[idx] = acc;
}

// ---------------- final: out = x + (We*alpha)@x + cv, via HMMA ----------------
__global__ void __launch_bounds__(256) k_final_mma(const float* __restrict__ x,
                                                   float* __restrict__ out) {
    __shared__ __align__(16) __nv_bfloat16 sAh[128 * 40], sAl[128 * 40];
    __shared__ __align__(16) __nv_bfloat16 sBh[32 * 136], sBl[32 * 136];
    __shared__ float sAlpha[CCH];

    int tid = threadIdx.x, lane = tid & 31, wid = tid >> 5;
    int bn = blockIdx.x, bo = blockIdx.y, b = blockIdx.z;

    for (int i = tid; i < CCH; i += 256) sAlpha[i] = g_alpha[b * CCH + i];

    // A loader: row o = tid>>1 (0..127), cols (tid&1)*16 .. +15
    int alr = tid >> 1, alcol = (tid & 1) << 4;
    const float* Wrow = g_We + ((size_t)b * CCH + bo * 128 + alr) * CCH + alcol;
    // B loader: k = tid>>3 (0..31), cols n = (tid&7)*16 .. +15
    int bkr = tid >> 3, bncol = (tid & 7) << 4;
    const float* Brow = x + ((size_t)b * CCH + bkr) * NSP + bn * 128 + bncol;

    const int NCH = CCH / GKC;   // 16
    float av[16], bv[16];
#pragma unroll
    for (int q = 0; q < 4; q++) {
        *(float4*)&av[4 * q] = *(const float4*)(Wrow + 4 * q);
        *(float4*)&bv[4 * q] = *(const float4*)(Brow + 4 * q);
    }

    float acc[2][8][4];
#pragma unroll
    for (int i = 0; i < 2; i++)
#pragma unroll
        for (int j = 0; j < 8; j++)
#pragma unroll
            for (int k = 0; k < 4; k++) acc[i][j][k] = 0.f;

    int wm = (wid & 3) * 32, wn = (wid >> 2) * 64;
    uint32_t aoff[2], boff[4];
#pragma unroll
    for (int mt = 0; mt < 2; mt++)
        aoff[mt] = ((wm + mt * 16 + (lane & 15)) * 40 + ((lane >> 4) << 3)) * 2;
#pragma unroll
    for (int np = 0; np < 4; np++)
        boff[np] = (((lane & 7) + ((lane >> 3) & 1) * 8) * 136 +
                    wn + np * 16 + ((lane >> 4) << 3)) * 2;

    uint32_t sAhA = smem_u32(sAh), sAlA = smem_u32(sAl);
    uint32_t sBhA = smem_u32(sBh), sBlA = smem_u32(sBl);
    uint32_t aso = (alr * 40 + alcol) * 2;
    uint32_t bso = (bkr * 136 + bncol) * 2;

    for (int ch = 0; ch < NCH; ch++) {
        int kb = ch * GKC;
        __syncthreads();
        {
            float sv[16];
#pragma unroll
            for (int i = 0; i < 16; i++) sv[i] = av[i] * sAlpha[kb + alcol + i];
            *(uint4*)((char*)sAh + aso)      = pack8_hi(sv);
            *(uint4*)((char*)sAh + aso + 16) = pack8_hi(sv + 8);
            *(uint4*)((char*)sAl + aso)      = pack8_lo(sv);
            *(uint4*)((char*)sAl + aso + 16) = pack8_lo(sv + 8);
        }
        *(uint4*)((char*)sBh + bso)      = pack8_hi(bv);
        *(uint4*)((char*)sBh + bso + 16) = pack8_hi(bv + 8);
        *(uint4*)((char*)sBl + bso)      = pack8_lo(bv);
        *(uint4*)((char*)sBl + bso + 16) = pack8_lo(bv + 8);
        __syncthreads();
        if (ch + 1 < NCH) {
#pragma unroll
            for (int q = 0; q < 4; q++) {
                *(float4*)&av[4 * q] = *(const float4*)(Wrow + (ch + 1) * GKC + 4 * q);
                *(float4*)&bv[4 * q] = *(const float4*)(Brow + (size_t)(ch + 1) * GKC * NSP + 4 * q);
            }
        }
#pragma unroll
        for (int k0 = 0; k0 < GKC; k0 += 16) {
            uint32_t ah[2][4], al[2][4];
#pragma unroll
            for (int mt = 0; mt < 2; mt++) {
                ldsm_x4(ah[mt], sAhA + aoff[mt] + k0 * 2);
                ldsm_x4(al[mt], sAlA + aoff[mt] + k0 * 2);
            }
            uint32_t bh[8][2], bl[8][2];
#pragma unroll
            for (int np = 0; np < 4; np++) {
                uint32_t r[4];
                ldsm_x4_t(r, sBhA + boff[np] + k0 * 136 * 2);
                bh[2 * np][0] = r[0]; bh[2 * np][1] = r[1];
                bh[2 * np + 1][0] = r[2]; bh[2 * np + 1][1] = r[3];
                ldsm_x4_t(r, sBlA + boff[np] + k0 * 136 * 2);
                bl[2 * np][0] = r[0]; bl[2 * np][1] = r[1];
                bl[2 * np + 1][0] = r[2]; bl[2 * np + 1][1] = r[3];
            }
#pragma unroll
            for (int mt = 0; mt < 2; mt++)
#pragma unroll
                for (int nt = 0; nt < 8; nt++) {
                    mma_bf16(acc[mt][nt], ah[mt], bh[nt]);
                    mma_bf16(acc[mt][nt], ah[mt], bl[nt]);
                    mma_bf16(acc[mt][nt], al[mt], bh[nt]);
                }
        }
    }

    const float* cvp = g_cv + b * CCH;
    int g = lane >> 2, c2 = (lane & 3) << 1;
#pragma unroll
    for (int mt = 0; mt < 2; mt++) {
        int gi = bo * 128 + wm + mt * 16 + g;
        float cf0 = cvp[gi], cf8 = cvp[gi + 8];
        size_t r0 = ((size_t)b * CCH + gi) * NSP;
        size_t r8 = r0 + (size_t)8 * NSP;
#pragma unroll
        for (int nt = 0; nt < 8; nt++) {
            int gj = bn * 128 + wn + nt * 8 + c2;
            float* p = acc[mt][nt];
            float2 x0 = *(const float2*)(x + r0 + gj);
            float2 x8 = *(const float2*)(x + r8 + gj);
            float2 o0 = make_float2(x0.x + p[0] + cf0, x0.y + p[1] + cf0);
            float2 o8 = make_float2(x8.x + p[2] + cf8, x8.y + p[3] + cf8);
            *(float2*)(out + r0 + gj) = o0;
            *(float2*)(out + r8 + gj) = o8;
        }
    }
}

// ---------------- launch ------------------------------------------------------
extern "C" void kernel_launch(void* const* d_in, const int* in_sizes, int n_in,
                              void* d_out, int out_size) {
    const float* x      = (const float*)d_in[0];
    const float* gn_w   = (const float*)d_in[1];
    const float* gn_b   = (const float*)d_in[2];
    const float* qkv_w  = (const float*)d_in[3];
    const float* qkv_b  = (const float*)d_in[4];
    const float* proj_w = (const float*)d_in[5];
    const float* proj_b = (const float*)d_in[6];
    float* out = (float*)d_out;

    k_chansum<<<BATCH * CCH, 256>>>(x);
    k_stats<<<1, 256>>>(gn_w, gn_b);
    k_gram_mma<<<dim3(10, KSPL, BATCH), 256>>>(x);
    k_gsum<<<(int)(((size_t)BATCH * CCH * CCH) / 256), 256>>>();
    k_uv<<<8, 256>>>(qkv_w);
    k_small_nn<<<dim3(8, 8, BATCH), 256>>>(0, qkv_w, proj_w);   // P = Wq @ G
    k_nt_logits<<<dim3(8, 8, BATCH), 256>>>(qkv_w, qkv_b);      // L = scale*(P@Wk^T + bias)
    k_softmax<<<BATCH * CCH, 256>>>();                           // A = softmax(L)
    k_small_nn<<<dim3(8, 8, BATCH), 256>>>(1, qkv_w, proj_w);   // M = proj_w @ A
    k_small_nn<<<dim3(8, 8, BATCH), 256>>>(2, qkv_w, proj_w);   // We = M @ Wv
    k_cv<<<4, 256>>>(qkv_b, proj_b);
    k_final_mma<<<dim3(NSP / 128, CCH / 128, BATCH), 256>>>(x, out);
}